// round 8
// baseline (speedup 1.0000x reference)
#include <cuda_runtime.h>
#include <cuda_bf16.h>
#include <cstdint>

// ---------------------------------------------------------------------------
// VQ-VAE VectorQuantizer on GB300 (sm_103, no 'a' features available in PTX).
// Strategy: warp-level bf16 mma.sync computes approximate distances; rigorous
// error window collects a tiny candidate set per token; exact sequential
// fp32-FMA recompute (bit-identical to XLA, proven rel_err=0.0) picks the
// final argmin with first-index tie-break.
// R8: fp-loop unrolled x4 -> 8 accumulator chains + 4 LDSM streams per warp
// to hide HMMA/LDSM latency at 2 warps/SMSP.
// ---------------------------------------------------------------------------

#define N_TOK   16384
#define N_CODE  8192
#define C_DIM   256
#define Q_ELEMS 4194304      // 16*256*32*32
#define ENC_OFF 4194306LL    // 1 + Q_ELEMS + 1
#define CAP     96

__device__ float    g_S[N_TOK];
__device__ float    g_L1[N_TOK];
__device__ float    g_E2[N_CODE];
__device__ int      g_idx[N_TOK];
__device__ int      g_counts[N_CODE];
__device__ double   g_loss_part[16384];
__device__ int      g_cand[N_TOK][CAP];
__device__ int      g_cnt[N_TOK];
__device__ unsigned g_maxe_bits;

__device__ __forceinline__ float f_inf() { return __int_as_float(0x7f800000); }

__device__ __forceinline__ uint32_t smem_u32(const void* p) {
    uint32_t a;
    asm("{ .reg .u64 t; cvta.to.shared.u64 t, %1; cvt.u32.u64 %0, t; }"
        : "=r"(a) : "l"(p));
    return a;
}
#define LDSM_X4(r0, r1, r2, r3, addr)                                          \
    asm volatile("ldmatrix.sync.aligned.m8n8.x4.shared.b16 {%0,%1,%2,%3}, [%4];" \
        : "=r"(r0), "=r"(r1), "=r"(r2), "=r"(r3) : "r"(addr))
#define MMA_BF16(c0, c1, c2, c3, a0, a1, a2, a3, b0, b1)                       \
    asm volatile("mma.sync.aligned.m16n8k16.row.col.f32.bf16.bf16.f32 "       \
        "{%0,%1,%2,%3},{%4,%5,%6,%7},{%8,%9},{%0,%1,%2,%3};"                  \
        : "+f"(c0), "+f"(c1), "+f"(c2), "+f"(c3)                               \
        : "r"(a0), "r"(a1), "r"(a2), "r"(a3), "r"(b0), "r"(b1))

// ---------------------------------------------------------------- reset ----
__global__ void k_reset() {
    int t = blockIdx.x * blockDim.x + threadIdx.x;
    if (t < N_CODE) g_counts[t] = 0;
    if (t < N_TOK)  g_cnt[t] = 0;
    if (t == 0)     g_maxe_bits = 0;
}

// ----------------------------------------------- S = sum(x*x), L1 = sum|x| --
__global__ void k_S(const float* __restrict__ x) {
    int n = blockIdx.x * blockDim.x + threadIdx.x;
    if (n >= N_TOK) return;
    int b = n >> 10, hw = n & 1023;
    const float* p = x + (size_t)b * 262144 + hw;
    float acc = 0.0f, l1 = 0.0f;
    for (int c = 0; c < C_DIM; c++) {
        float v = p[(size_t)c * 1024];
        acc = __fadd_rn(acc, __fmul_rn(v, v));
        l1 += fabsf(v);
    }
    g_S[n] = acc;
    g_L1[n] = l1;
}

// ----------------------------------------- E2 = sum(e*e), track max |e| ----
__global__ void k_E2(const float* __restrict__ emb) {
    int k = blockIdx.x * blockDim.x + threadIdx.x;
    if (k >= N_CODE) return;
    const float* p = emb + (size_t)k * C_DIM;
    float acc = 0.0f, mx = 0.0f;
    for (int c = 0; c < C_DIM; c++) {
        float v = p[c];
        acc = __fadd_rn(acc, __fmul_rn(v, v));
        mx = fmaxf(mx, fabsf(v));
    }
    g_E2[k] = acc;
    atomicMax(&g_maxe_bits, __float_as_uint(mx));   // positive: uint order == float order
}

// ----------------------- bf16 mma.sync approx distances + candidate filter --
// CTA = 128 tokens x all 8192 codes (64 n-tiles of 128). A resident in smem
// (bf16, padded 528B rows), E double-buffered. 8 warps, warp tile 16 tokens x
// 128 codes per n-tile, processed as 2 quads of 4 concurrent fp-groups.
#define RS      528              // padded row stride bytes (264 halves)
#define SM_E2S  0                // 2 x 128 f32
#define SM_A    1024             // 128 rows * 528B = 67584
#define SM_EB0  68608
#define SM_EB1  136192
#define SMEM_DYN 203776

__global__ void __launch_bounds__(256, 1)
k_mma(const float* __restrict__ x, const float* __restrict__ emb) {
    extern __shared__ char sm[];
    float* e2s = (float*)(sm + SM_E2S);
    const uint32_t sb = smem_u32(sm);
    const uint32_t sA = sb + SM_A;

    const int tid = threadIdx.x, w = tid >> 5, lane = tid & 31;
    const int mbase = blockIdx.x * 128;
    const int b     = mbase >> 10;
    const int hw0   = mbase & 1023;
    const float* xb = x + (size_t)b * 262144 + hw0;

    // ---- stage A: 128 tokens x 256 c, bf16, padded rows ----
    for (int i = tid; i < 128 * 32; i += 256) {
        int m = i & 127, c0 = (i >> 7) * 8;
        float v0 = xb[(size_t)(c0 + 0) * 1024 + m];
        float v1 = xb[(size_t)(c0 + 1) * 1024 + m];
        float v2 = xb[(size_t)(c0 + 2) * 1024 + m];
        float v3 = xb[(size_t)(c0 + 3) * 1024 + m];
        float v4 = xb[(size_t)(c0 + 4) * 1024 + m];
        float v5 = xb[(size_t)(c0 + 5) * 1024 + m];
        float v6 = xb[(size_t)(c0 + 6) * 1024 + m];
        float v7 = xb[(size_t)(c0 + 7) * 1024 + m];
        __nv_bfloat162 h0 = __floats2bfloat162_rn(v0, v1);
        __nv_bfloat162 h1 = __floats2bfloat162_rn(v2, v3);
        __nv_bfloat162 h2 = __floats2bfloat162_rn(v4, v5);
        __nv_bfloat162 h3 = __floats2bfloat162_rn(v6, v7);
        uint4 pk;
        pk.x = *(uint32_t*)&h0; pk.y = *(uint32_t*)&h1;
        pk.z = *(uint32_t*)&h2; pk.w = *(uint32_t*)&h3;
        *(uint4*)(sm + SM_A + m * RS + c0 * 2) = pk;
    }

    // ---- E tile staging helper (n-tile nt -> buffer buf) ----
    auto stage_E = [&](int nt, int buf) {
        const int kb = nt * 128;
        char* eb = sm + (buf ? SM_EB1 : SM_EB0);
        for (int i = tid; i < 4096; i += 256) {          // 128 rows x 32 c-segs
            int row = i >> 5, c0 = (i & 31) * 8;
            const float4 v0 = *(const float4*)&emb[(size_t)(kb + row) * 256 + c0];
            const float4 v1 = *(const float4*)&emb[(size_t)(kb + row) * 256 + c0 + 4];
            __nv_bfloat162 h0 = __floats2bfloat162_rn(v0.x, v0.y);
            __nv_bfloat162 h1 = __floats2bfloat162_rn(v0.z, v0.w);
            __nv_bfloat162 h2 = __floats2bfloat162_rn(v1.x, v1.y);
            __nv_bfloat162 h3 = __floats2bfloat162_rn(v1.z, v1.w);
            uint4 pk;
            pk.x = *(uint32_t*)&h0; pk.y = *(uint32_t*)&h1;
            pk.z = *(uint32_t*)&h2; pk.w = *(uint32_t*)&h3;
            *(uint4*)(eb + row * RS + c0 * 2) = pk;
        }
        for (int i = tid; i < 128; i += 256) e2s[buf * 128 + i] = g_E2[kb + i];
    };

    stage_E(0, 0);
    __syncthreads();

    // ---- hoist A fragments: 16 k-steps x 4 regs ----
    uint32_t a[16][4];
    {
        uint32_t abase = sA + (uint32_t)(w * 16 + (lane & 15)) * RS + ((lane >> 4) & 1) * 16;
#pragma unroll
        for (int k = 0; k < 16; k++)
            LDSM_X4(a[k][0], a[k][1], a[k][2], a[k][3], abase + k * 32);
    }

    // ---- per-token filter state (2 token rows per lane) ----
    const int   tok0 = mbase + w * 16 + (lane >> 2);
    const int   tok1 = tok0 + 8;
    const float S0 = g_S[tok0], S1 = g_S[tok1];
    const float maxe = __uint_as_float(g_maxe_bits);
    const float W0 = __fmaf_rn(0.0313f * maxe, g_L1[tok0], 1.3e-4f);
    const float W1 = __fmaf_rn(0.0313f * maxe, g_L1[tok1], 1.3e-4f);
    float rm0 = f_inf(), rm1 = f_inf(), thr0 = f_inf(), thr1 = f_inf();

    for (int nt = 0; nt < 64; nt++) {
        if (nt + 1 < 64) stage_E(nt + 1, (nt + 1) & 1);

        const uint32_t eB = sb + ((nt & 1) ? SM_EB1 : SM_EB0);
        const float*   e2 = e2s + (nt & 1) * 128;
        const int      kb = nt * 128;
        const uint32_t bbase = eB + (uint32_t)(lane & 15) * RS + ((lane >> 4) & 1) * 16;

#pragma unroll 1
        for (int fq = 0; fq < 2; fq++) {
            // 4 concurrent fp-groups -> 8 independent accumulator chains
            float acc[4][8];
#pragma unroll
            for (int q = 0; q < 4; q++)
#pragma unroll
                for (int r = 0; r < 8; r++) acc[q][r] = 0.f;

            const uint32_t bq = bbase + (uint32_t)fq * (64 * RS);
#pragma unroll
            for (int k = 0; k < 16; k++) {
#pragma unroll
                for (int q = 0; q < 4; q++) {
                    uint32_t b0, b1, b2, b3;
                    LDSM_X4(b0, b1, b2, b3, bq + (uint32_t)q * (16 * RS) + k * 32);
                    MMA_BF16(acc[q][0], acc[q][1], acc[q][2], acc[q][3],
                             a[k][0], a[k][1], a[k][2], a[k][3], b0, b2);
                    MMA_BF16(acc[q][4], acc[q][5], acc[q][6], acc[q][7],
                             a[k][0], a[k][1], a[k][2], a[k][3], b1, b3);
                }
            }

            // epilogue: d = (S + E2) - 2*dot ; capture candidates
#pragma unroll
            for (int q = 0; q < 4; q++) {
                const int fp = fq * 4 + q;
#pragma unroll
                for (int h = 0; h < 2; h++) {
                    const int   f   = fp * 2 + h;
                    const int   cA  = f * 8 + (lane & 3) * 2;
                    const float e2a = e2[cA], e2b = e2[cA + 1];
                    const int   colA = kb + cA, colB = colA + 1;
                    const float dotA0 = h ? acc[q][4] : acc[q][0];
                    const float dotB0 = h ? acc[q][5] : acc[q][1];
                    const float dotA1 = h ? acc[q][6] : acc[q][2];
                    const float dotB1 = h ? acc[q][7] : acc[q][3];
                    float dA0 = __fsub_rn(__fadd_rn(S0, e2a), __fmul_rn(2.0f, dotA0));
                    float dB0 = __fsub_rn(__fadd_rn(S0, e2b), __fmul_rn(2.0f, dotB0));
                    float dA1 = __fsub_rn(__fadd_rn(S1, e2a), __fmul_rn(2.0f, dotA1));
                    float dB1 = __fsub_rn(__fadd_rn(S1, e2b), __fmul_rn(2.0f, dotB1));
                    if (dA0 < thr0) {
                        int s = atomicAdd(&g_cnt[tok0], 1);
                        if (s < CAP) g_cand[tok0][s] = colA;
                        if (dA0 < rm0) { rm0 = dA0; thr0 = __fadd_rn(dA0, W0); }
                    }
                    if (dB0 < thr0) {
                        int s = atomicAdd(&g_cnt[tok0], 1);
                        if (s < CAP) g_cand[tok0][s] = colB;
                        if (dB0 < rm0) { rm0 = dB0; thr0 = __fadd_rn(dB0, W0); }
                    }
                    if (dA1 < thr1) {
                        int s = atomicAdd(&g_cnt[tok1], 1);
                        if (s < CAP) g_cand[tok1][s] = colA;
                        if (dA1 < rm1) { rm1 = dA1; thr1 = __fadd_rn(dA1, W1); }
                    }
                    if (dB1 < thr1) {
                        int s = atomicAdd(&g_cnt[tok1], 1);
                        if (s < CAP) g_cand[tok1][s] = colB;
                        if (dB1 < rm1) { rm1 = dB1; thr1 = __fadd_rn(dB1, W1); }
                    }
                }
            }
        }
        // tighten thresholds across the 4 lanes sharing the same token rows
#pragma unroll
        for (int off = 1; off < 4; off <<= 1) {
            rm0 = fminf(rm0, __shfl_xor_sync(0xffffffff, rm0, off));
            rm1 = fminf(rm1, __shfl_xor_sync(0xffffffff, rm1, off));
        }
        thr0 = __fadd_rn(rm0, W0);
        thr1 = __fadd_rn(rm1, W1);
        __syncthreads();
    }
}

// ------------------------------------- exact refinement (bit-exact argmin) --
__global__ void k_refine(const float* __restrict__ x, const float* __restrict__ emb) {
    __shared__ float xs[8][256];
    const int w = threadIdx.x >> 5, lane = threadIdx.x & 31;
    const int n = blockIdx.x * 8 + w;
    const int b = n >> 10, hw = n & 1023;
    const float* xb = x + (size_t)b * 262144 + hw;
    for (int c = lane; c < 256; c += 32) xs[w][c] = xb[(size_t)c * 1024];
    __syncwarp();

    const float S = g_S[n];
    const int cnt = g_cnt[n];
    float bd = f_inf(); int bi = 0x7fffffff;

    auto exact_d = [&](int k) -> float {
        const float* e = emb + (size_t)k * 256;
        float acc = 0.0f;
#pragma unroll 8
        for (int c = 0; c < 256; c++)
            acc = __fmaf_rn(xs[w][c], e[c], acc);       // sequential chain, c asc
        float t = __fadd_rn(S, g_E2[k]);
        return __fsub_rn(t, __fmul_rn(2.0f, acc));
    };

    if (cnt > CAP) {                                    // overflow: full scan
        for (int k = lane; k < N_CODE; k += 32) {
            float d = exact_d(k);
            if (d < bd || (d == bd && k < bi)) { bd = d; bi = k; }
        }
    } else {
        for (int ci = lane; ci < cnt; ci += 32) {
            int k = g_cand[n][ci];
            float d = exact_d(k);
            if (d < bd || (d == bd && k < bi)) { bd = d; bi = k; }
        }
    }
#pragma unroll
    for (int off = 16; off > 0; off >>= 1) {
        float od = __shfl_down_sync(0xffffffff, bd, off);
        int   oi = __shfl_down_sync(0xffffffff, bi, off);
        if (od < bd || (od == bd && oi < bi)) { bd = od; bi = oi; }
    }
    if (lane == 0) g_idx[n] = bi;
}

// --------------------------------- quantized output + loss partial ----------
__global__ void k_quant(const float* __restrict__ x, const float* __restrict__ emb,
                        float* __restrict__ outq) {
    int l = blockIdx.x * blockDim.x + threadIdx.x;
    double part = 0.0;
    if (l < Q_ELEMS) {
        int b   = l >> 18;
        int rem = l & 262143;
        int c   = rem >> 10;
        int hw  = rem & 1023;
        int n   = (b << 10) + hw;
        int idx = g_idx[n];
        float q    = __ldg(&emb[(size_t)idx * C_DIM + c]);
        float xv   = x[l];
        float diff = __fsub_rn(q, xv);
        outq[l]    = __fadd_rn(xv, diff);               // straight-through
        part = (double)__fmul_rn(diff, diff);
    }
    __shared__ double sred[256];
    sred[threadIdx.x] = part;
    __syncthreads();
    for (int s = 128; s > 0; s >>= 1) {
        if (threadIdx.x < s) sred[threadIdx.x] += sred[threadIdx.x + s];
        __syncthreads();
    }
    if (threadIdx.x == 0) g_loss_part[blockIdx.x] = sred[0];
}

// ------------------------------------------- one-hot scatter + histogram ----
__global__ void k_enc(float* __restrict__ out, long long enc_elems) {
    int n = blockIdx.x * blockDim.x + threadIdx.x;
    if (n >= N_TOK) return;
    int idx = g_idx[n];
    long long off = (long long)n * N_CODE + idx;
    if (off < enc_elems) out[ENC_OFF + off] = 1.0f;
    atomicAdd(&g_counts[idx], 1);
}

// -------------------------------------------------- loss + perplexity -------
__global__ void k_final(float* __restrict__ out, int has_full) {
    __shared__ double sred[256];
    int t = threadIdx.x;
    double acc = 0.0;
    for (int k = t; k < N_CODE; k += 256) {
        float p  = (float)g_counts[k] * (1.0f / 16384.0f);
        float lg = logf(__fadd_rn(p, 1e-10f));
        acc += (double)__fmul_rn(p, lg);
    }
    sred[t] = acc; __syncthreads();
    for (int s = 128; s > 0; s >>= 1) {
        if (t < s) sred[t] += sred[t + s];
        __syncthreads();
    }
    double H = sred[0];

    double lacc = 0.0;
    for (int k = t; k < 16384; k += 256) lacc += g_loss_part[k];
    __syncthreads();
    sred[t] = lacc; __syncthreads();
    for (int s = 128; s > 0; s >>= 1) {
        if (t < s) sred[t] += sred[t + s];
        __syncthreads();
    }
    if (t == 0) {
        float m    = (float)(sred[0] / (double)Q_ELEMS);
        float loss = __fadd_rn(m, __fmul_rn(0.25f, m));
        out[0] = loss;
        if (has_full) out[1 + Q_ELEMS] = expf(-(float)H);
    }
}

// ---------------------------------------------------------------------------
extern "C" void kernel_launch(void* const* d_in, const int* in_sizes, int n_in,
                              void* d_out, int out_size) {
    const float* x   = (const float*)d_in[0];
    const float* emb = (const float*)d_in[1];
    if (n_in >= 2 && in_sizes[0] == N_CODE * C_DIM && in_sizes[1] == Q_ELEMS) {
        const float* t = x; x = emb; emb = t;
    }
    float* out = (float*)d_out;

    long long enc_elems = (long long)out_size - ENC_OFF;
    int has_full = (enc_elems > 0);

    cudaFuncSetAttribute(k_mma, cudaFuncAttributeMaxDynamicSharedMemorySize,
                         SMEM_DYN);

    if (has_full)
        cudaMemsetAsync(out + ENC_OFF, 0, (size_t)enc_elems * sizeof(float), 0);

    k_reset <<<64, 256>>>();
    k_S     <<<N_TOK / 256, 256>>>(x);
    k_E2    <<<N_CODE / 256, 256>>>(emb);
    k_mma   <<<N_TOK / 128, 256, SMEM_DYN>>>(x, emb);
    k_refine<<<N_TOK / 8, 256>>>(x, emb);
    k_quant <<<Q_ELEMS / 256, 256>>>(x, emb, out + 1);
    k_enc   <<<N_TOK / 256, 256>>>(out, has_full ? enc_elems : 0);
    k_final <<<1, 256>>>(out, has_full);
}

// round 9
// speedup vs baseline: 1.0367x; 1.0367x over previous
#include <cuda_runtime.h>
#include <cuda_bf16.h>
#include <cstdint>

// ---------------------------------------------------------------------------
// VQ-VAE VectorQuantizer on GB300 (sm_103, no 'a' features available in PTX).
// bf16 mma.sync approx distances -> rigorous window candidate filter ->
// exact sequential fp32-FMA refine (bit-identical to XLA, rel_err=0.0).
// R9: (1) k_mma: double-buffered B-fragment prefetch kills LDSM->HMMA RAW;
//     (2) k_quant: smem row-gather (coalesced) instead of per-thread scatter.
// ---------------------------------------------------------------------------

#define N_TOK   16384
#define N_CODE  8192
#define C_DIM   256
#define Q_ELEMS 4194304      // 16*256*32*32
#define ENC_OFF 4194306LL    // 1 + Q_ELEMS + 1
#define CAP     96
#define QPARTS  512

__device__ float    g_S[N_TOK];
__device__ float    g_L1[N_TOK];
__device__ float    g_E2[N_CODE];
__device__ int      g_idx[N_TOK];
__device__ int      g_counts[N_CODE];
__device__ double   g_loss_part[QPARTS];
__device__ int      g_cand[N_TOK][CAP];
__device__ int      g_cnt[N_TOK];
__device__ unsigned g_maxe_bits;

__device__ __forceinline__ float f_inf() { return __int_as_float(0x7f800000); }

__device__ __forceinline__ uint32_t smem_u32(const void* p) {
    uint32_t a;
    asm("{ .reg .u64 t; cvta.to.shared.u64 t, %1; cvt.u32.u64 %0, t; }"
        : "=r"(a) : "l"(p));
    return a;
}
#define LDSM_X4(r0, r1, r2, r3, addr)                                          \
    asm volatile("ldmatrix.sync.aligned.m8n8.x4.shared.b16 {%0,%1,%2,%3}, [%4];" \
        : "=r"(r0), "=r"(r1), "=r"(r2), "=r"(r3) : "r"(addr))
#define MMA_BF16(c0, c1, c2, c3, a0, a1, a2, a3, b0, b1)                       \
    asm volatile("mma.sync.aligned.m16n8k16.row.col.f32.bf16.bf16.f32 "       \
        "{%0,%1,%2,%3},{%4,%5,%6,%7},{%8,%9},{%0,%1,%2,%3};"                  \
        : "+f"(c0), "+f"(c1), "+f"(c2), "+f"(c3)                               \
        : "r"(a0), "r"(a1), "r"(a2), "r"(a3), "r"(b0), "r"(b1))

// ---------------------------------------------------------------- reset ----
__global__ void k_reset() {
    int t = blockIdx.x * blockDim.x + threadIdx.x;
    if (t < N_CODE) g_counts[t] = 0;
    if (t < N_TOK)  g_cnt[t] = 0;
    if (t == 0)     g_maxe_bits = 0;
}

// ----------------------------------------------- S = sum(x*x), L1 = sum|x| --
__global__ void k_S(const float* __restrict__ x) {
    int n = blockIdx.x * blockDim.x + threadIdx.x;
    if (n >= N_TOK) return;
    int b = n >> 10, hw = n & 1023;
    const float* p = x + (size_t)b * 262144 + hw;
    float acc = 0.0f, l1 = 0.0f;
    for (int c = 0; c < C_DIM; c++) {
        float v = p[(size_t)c * 1024];
        acc = __fadd_rn(acc, __fmul_rn(v, v));
        l1 += fabsf(v);
    }
    g_S[n] = acc;
    g_L1[n] = l1;
}

// ----------------------------------------- E2 = sum(e*e), track max |e| ----
__global__ void k_E2(const float* __restrict__ emb) {
    int k = blockIdx.x * blockDim.x + threadIdx.x;
    if (k >= N_CODE) return;
    const float* p = emb + (size_t)k * C_DIM;
    float acc = 0.0f, mx = 0.0f;
    for (int c = 0; c < C_DIM; c++) {
        float v = p[c];
        acc = __fadd_rn(acc, __fmul_rn(v, v));
        mx = fmaxf(mx, fabsf(v));
    }
    g_E2[k] = acc;
    atomicMax(&g_maxe_bits, __float_as_uint(mx));   // positive: uint order == float order
}

// ----------------------- bf16 mma.sync approx distances + candidate filter --
#define RS      528              // padded row stride bytes (264 halves)
#define SM_E2S  0                // 2 x 128 f32
#define SM_A    1024             // 128 rows * 528B = 67584
#define SM_EB0  68608
#define SM_EB1  136192
#define SMEM_DYN 203776

__global__ void __launch_bounds__(256, 1)
k_mma(const float* __restrict__ x, const float* __restrict__ emb) {
    extern __shared__ char sm[];
    float* e2s = (float*)(sm + SM_E2S);
    const uint32_t sb = smem_u32(sm);
    const uint32_t sA = sb + SM_A;

    const int tid = threadIdx.x, w = tid >> 5, lane = tid & 31;
    const int mbase = blockIdx.x * 128;
    const int b     = mbase >> 10;
    const int hw0   = mbase & 1023;
    const float* xb = x + (size_t)b * 262144 + hw0;

    // ---- stage A: 128 tokens x 256 c, bf16, padded rows ----
    for (int i = tid; i < 128 * 32; i += 256) {
        int m = i & 127, c0 = (i >> 7) * 8;
        float v0 = xb[(size_t)(c0 + 0) * 1024 + m];
        float v1 = xb[(size_t)(c0 + 1) * 1024 + m];
        float v2 = xb[(size_t)(c0 + 2) * 1024 + m];
        float v3 = xb[(size_t)(c0 + 3) * 1024 + m];
        float v4 = xb[(size_t)(c0 + 4) * 1024 + m];
        float v5 = xb[(size_t)(c0 + 5) * 1024 + m];
        float v6 = xb[(size_t)(c0 + 6) * 1024 + m];
        float v7 = xb[(size_t)(c0 + 7) * 1024 + m];
        __nv_bfloat162 h0 = __floats2bfloat162_rn(v0, v1);
        __nv_bfloat162 h1 = __floats2bfloat162_rn(v2, v3);
        __nv_bfloat162 h2 = __floats2bfloat162_rn(v4, v5);
        __nv_bfloat162 h3 = __floats2bfloat162_rn(v6, v7);
        uint4 pk;
        pk.x = *(uint32_t*)&h0; pk.y = *(uint32_t*)&h1;
        pk.z = *(uint32_t*)&h2; pk.w = *(uint32_t*)&h3;
        *(uint4*)(sm + SM_A + m * RS + c0 * 2) = pk;
    }

    // ---- E tile staging helper (n-tile nt -> buffer buf) ----
    auto stage_E = [&](int nt, int buf) {
        const int kb = nt * 128;
        char* eb = sm + (buf ? SM_EB1 : SM_EB0);
        for (int i = tid; i < 4096; i += 256) {          // 128 rows x 32 c-segs
            int row = i >> 5, c0 = (i & 31) * 8;
            const float4 v0 = *(const float4*)&emb[(size_t)(kb + row) * 256 + c0];
            const float4 v1 = *(const float4*)&emb[(size_t)(kb + row) * 256 + c0 + 4];
            __nv_bfloat162 h0 = __floats2bfloat162_rn(v0.x, v0.y);
            __nv_bfloat162 h1 = __floats2bfloat162_rn(v0.z, v0.w);
            __nv_bfloat162 h2 = __floats2bfloat162_rn(v1.x, v1.y);
            __nv_bfloat162 h3 = __floats2bfloat162_rn(v1.z, v1.w);
            uint4 pk;
            pk.x = *(uint32_t*)&h0; pk.y = *(uint32_t*)&h1;
            pk.z = *(uint32_t*)&h2; pk.w = *(uint32_t*)&h3;
            *(uint4*)(eb + row * RS + c0 * 2) = pk;
        }
        for (int i = tid; i < 128; i += 256) e2s[buf * 128 + i] = g_E2[kb + i];
    };

    stage_E(0, 0);
    __syncthreads();

    // ---- hoist A fragments: 16 k-steps x 4 regs ----
    uint32_t a[16][4];
    {
        uint32_t abase = sA + (uint32_t)(w * 16 + (lane & 15)) * RS + ((lane >> 4) & 1) * 16;
#pragma unroll
        for (int k = 0; k < 16; k++)
            LDSM_X4(a[k][0], a[k][1], a[k][2], a[k][3], abase + k * 32);
    }

    // ---- per-token filter state (2 token rows per lane) ----
    const int   tok0 = mbase + w * 16 + (lane >> 2);
    const int   tok1 = tok0 + 8;
    const float S0 = g_S[tok0], S1 = g_S[tok1];
    const float maxe = __uint_as_float(g_maxe_bits);
    const float W0 = __fmaf_rn(0.0313f * maxe, g_L1[tok0], 1.3e-4f);
    const float W1 = __fmaf_rn(0.0313f * maxe, g_L1[tok1], 1.3e-4f);
    float rm0 = f_inf(), rm1 = f_inf(), thr0 = f_inf(), thr1 = f_inf();

    for (int nt = 0; nt < 64; nt++) {
        if (nt + 1 < 64) stage_E(nt + 1, (nt + 1) & 1);

        const uint32_t eB = sb + ((nt & 1) ? SM_EB1 : SM_EB0);
        const float*   e2 = e2s + (nt & 1) * 128;
        const int      kb = nt * 128;
        const uint32_t bbase = eB + (uint32_t)(lane & 15) * RS + ((lane >> 4) & 1) * 16;

#pragma unroll 1
        for (int fq = 0; fq < 2; fq++) {
            float acc[4][8];
#pragma unroll
            for (int q = 0; q < 4; q++)
#pragma unroll
                for (int r = 0; r < 8; r++) acc[q][r] = 0.f;

            const uint32_t bq = bbase + (uint32_t)fq * (64 * RS);

            // double-buffered B fragments: prefetch k+1 while computing k
            uint32_t bb[2][4][4];
#pragma unroll
            for (int q = 0; q < 4; q++)
                LDSM_X4(bb[0][q][0], bb[0][q][1], bb[0][q][2], bb[0][q][3],
                        bq + (uint32_t)q * (16 * RS));
#pragma unroll
            for (int k = 0; k < 16; k++) {
                const int p = k & 1;
                if (k < 15) {
#pragma unroll
                    for (int q = 0; q < 4; q++)
                        LDSM_X4(bb[p ^ 1][q][0], bb[p ^ 1][q][1],
                                bb[p ^ 1][q][2], bb[p ^ 1][q][3],
                                bq + (uint32_t)q * (16 * RS) + (k + 1) * 32);
                }
#pragma unroll
                for (int q = 0; q < 4; q++) {
                    MMA_BF16(acc[q][0], acc[q][1], acc[q][2], acc[q][3],
                             a[k][0], a[k][1], a[k][2], a[k][3],
                             bb[p][q][0], bb[p][q][2]);
                    MMA_BF16(acc[q][4], acc[q][5], acc[q][6], acc[q][7],
                             a[k][0], a[k][1], a[k][2], a[k][3],
                             bb[p][q][1], bb[p][q][3]);
                }
            }

            // epilogue: d = (S + E2) - 2*dot ; capture candidates
#pragma unroll
            for (int q = 0; q < 4; q++) {
                const int fp = fq * 4 + q;
#pragma unroll
                for (int h = 0; h < 2; h++) {
                    const int   f   = fp * 2 + h;
                    const int   cA  = f * 8 + (lane & 3) * 2;
                    const float e2a = e2[cA], e2b = e2[cA + 1];
                    const int   colA = kb + cA, colB = colA + 1;
                    const float dotA0 = h ? acc[q][4] : acc[q][0];
                    const float dotB0 = h ? acc[q][5] : acc[q][1];
                    const float dotA1 = h ? acc[q][6] : acc[q][2];
                    const float dotB1 = h ? acc[q][7] : acc[q][3];
                    float dA0 = __fsub_rn(__fadd_rn(S0, e2a), __fmul_rn(2.0f, dotA0));
                    float dB0 = __fsub_rn(__fadd_rn(S0, e2b), __fmul_rn(2.0f, dotB0));
                    float dA1 = __fsub_rn(__fadd_rn(S1, e2a), __fmul_rn(2.0f, dotA1));
                    float dB1 = __fsub_rn(__fadd_rn(S1, e2b), __fmul_rn(2.0f, dotB1));
                    if (dA0 < thr0) {
                        int s = atomicAdd(&g_cnt[tok0], 1);
                        if (s < CAP) g_cand[tok0][s] = colA;
                        if (dA0 < rm0) { rm0 = dA0; thr0 = __fadd_rn(dA0, W0); }
                    }
                    if (dB0 < thr0) {
                        int s = atomicAdd(&g_cnt[tok0], 1);
                        if (s < CAP) g_cand[tok0][s] = colB;
                        if (dB0 < rm0) { rm0 = dB0; thr0 = __fadd_rn(dB0, W0); }
                    }
                    if (dA1 < thr1) {
                        int s = atomicAdd(&g_cnt[tok1], 1);
                        if (s < CAP) g_cand[tok1][s] = colA;
                        if (dA1 < rm1) { rm1 = dA1; thr1 = __fadd_rn(dA1, W1); }
                    }
                    if (dB1 < thr1) {
                        int s = atomicAdd(&g_cnt[tok1], 1);
                        if (s < CAP) g_cand[tok1][s] = colB;
                        if (dB1 < rm1) { rm1 = dB1; thr1 = __fadd_rn(dB1, W1); }
                    }
                }
            }
        }
        // tighten thresholds across the 4 lanes sharing the same token rows
#pragma unroll
        for (int off = 1; off < 4; off <<= 1) {
            rm0 = fminf(rm0, __shfl_xor_sync(0xffffffff, rm0, off));
            rm1 = fminf(rm1, __shfl_xor_sync(0xffffffff, rm1, off));
        }
        thr0 = __fadd_rn(rm0, W0);
        thr1 = __fadd_rn(rm1, W1);
        __syncthreads();
    }
}

// ------------------------------------- exact refinement (bit-exact argmin) --
__global__ void k_refine(const float* __restrict__ x, const float* __restrict__ emb) {
    __shared__ float xs[8][256];
    const int w = threadIdx.x >> 5, lane = threadIdx.x & 31;
    const int n = blockIdx.x * 8 + w;
    const int b = n >> 10, hw = n & 1023;
    const float* xb = x + (size_t)b * 262144 + hw;
    for (int c = lane; c < 256; c += 32) xs[w][c] = xb[(size_t)c * 1024];
    __syncwarp();

    const float S = g_S[n];
    const int cnt = g_cnt[n];
    float bd = f_inf(); int bi = 0x7fffffff;

    auto exact_d = [&](int k) -> float {
        const float* e = emb + (size_t)k * 256;
        float acc = 0.0f;
#pragma unroll 8
        for (int c = 0; c < 256; c++)
            acc = __fmaf_rn(xs[w][c], e[c], acc);       // sequential chain, c asc
        float t = __fadd_rn(S, g_E2[k]);
        return __fsub_rn(t, __fmul_rn(2.0f, acc));
    };

    if (cnt > CAP) {                                    // overflow: full scan
        for (int k = lane; k < N_CODE; k += 32) {
            float d = exact_d(k);
            if (d < bd || (d == bd && k < bi)) { bd = d; bi = k; }
        }
    } else {
        for (int ci = lane; ci < cnt; ci += 32) {
            int k = g_cand[n][ci];
            float d = exact_d(k);
            if (d < bd || (d == bd && k < bi)) { bd = d; bi = k; }
        }
    }
#pragma unroll
    for (int off = 16; off > 0; off >>= 1) {
        float od = __shfl_down_sync(0xffffffff, bd, off);
        int   oi = __shfl_down_sync(0xffffffff, bi, off);
        if (od < bd || (od == bd && oi < bi)) { bd = od; bi = oi; }
    }
    if (lane == 0) g_idx[n] = bi;
}

// ---------------- quantized output + loss partial (smem row-gather) ---------
// Block = 32 tokens. Gather the 32 selected emb rows into padded smem once
// (coalesced), then stream x / out fully coalesced.
__global__ void __launch_bounds__(256)
k_quant(const float* __restrict__ x, const float* __restrict__ emb,
        float* __restrict__ outq) {
    __shared__ float  er[32][257];
    __shared__ int    sidx[32];
    __shared__ double sred[256];
    const int tid = threadIdx.x;
    const int n0  = blockIdx.x * 32;
    const int b   = n0 >> 10;
    const int hw0 = n0 & 1023;

    if (tid < 32) sidx[tid] = g_idx[n0 + tid];
    __syncthreads();
    for (int i = tid; i < 32 * 256; i += 256) {
        int row = i >> 8, c = i & 255;
        er[row][c] = emb[(size_t)sidx[row] * 256 + c];
    }
    __syncthreads();

    const int hwl = tid & 31;
    double part = 0.0;
    for (int c = tid >> 5; c < 256; c += 8) {
        size_t l = (size_t)b * 262144 + (size_t)c * 1024 + hw0 + hwl;
        float xv   = x[l];
        float q    = er[hwl][c];
        float diff = __fsub_rn(q, xv);
        outq[l]    = __fadd_rn(xv, diff);               // straight-through
        part += (double)__fmul_rn(diff, diff);
    }

    sred[tid] = part;
    __syncthreads();
    for (int s = 128; s > 0; s >>= 1) {
        if (tid < s) sred[tid] += sred[tid + s];
        __syncthreads();
    }
    if (tid == 0) g_loss_part[blockIdx.x] = sred[0];
}

// ------------------------------------------- one-hot scatter + histogram ----
__global__ void k_enc(float* __restrict__ out, long long enc_elems) {
    int n = blockIdx.x * blockDim.x + threadIdx.x;
    if (n >= N_TOK) return;
    int idx = g_idx[n];
    long long off = (long long)n * N_CODE + idx;
    if (off < enc_elems) out[ENC_OFF + off] = 1.0f;
    atomicAdd(&g_counts[idx], 1);
}

// -------------------------------------------------- loss + perplexity -------
__global__ void k_final(float* __restrict__ out, int has_full) {
    __shared__ double sred[256];
    int t = threadIdx.x;
    double acc = 0.0;
    for (int k = t; k < N_CODE; k += 256) {
        float p  = (float)g_counts[k] * (1.0f / 16384.0f);
        float lg = logf(__fadd_rn(p, 1e-10f));
        acc += (double)__fmul_rn(p, lg);
    }
    sred[t] = acc; __syncthreads();
    for (int s = 128; s > 0; s >>= 1) {
        if (t < s) sred[t] += sred[t + s];
        __syncthreads();
    }
    double H = sred[0];

    double lacc = 0.0;
    for (int k = t; k < QPARTS; k += 256) lacc += g_loss_part[k];
    __syncthreads();
    sred[t] = lacc; __syncthreads();
    for (int s = 128; s > 0; s >>= 1) {
        if (t < s) sred[t] += sred[t + s];
        __syncthreads();
    }
    if (t == 0) {
        float m    = (float)(sred[0] / (double)Q_ELEMS);
        float loss = __fadd_rn(m, __fmul_rn(0.25f, m));
        out[0] = loss;
        if (has_full) out[1 + Q_ELEMS] = expf(-(float)H);
    }
}

// ---------------------------------------------------------------------------
extern "C" void kernel_launch(void* const* d_in, const int* in_sizes, int n_in,
                              void* d_out, int out_size) {
    const float* x   = (const float*)d_in[0];
    const float* emb = (const float*)d_in[1];
    if (n_in >= 2 && in_sizes[0] == N_CODE * C_DIM && in_sizes[1] == Q_ELEMS) {
        const float* t = x; x = emb; emb = t;
    }
    float* out = (float*)d_out;

    long long enc_elems = (long long)out_size - ENC_OFF;
    int has_full = (enc_elems > 0);

    cudaFuncSetAttribute(k_mma, cudaFuncAttributeMaxDynamicSharedMemorySize,
                         SMEM_DYN);

    if (has_full)
        cudaMemsetAsync(out + ENC_OFF, 0, (size_t)enc_elems * sizeof(float), 0);

    k_reset <<<64, 256>>>();
    k_S     <<<N_TOK / 256, 256>>>(x);
    k_E2    <<<N_CODE / 256, 256>>>(emb);
    k_mma   <<<N_TOK / 128, 256, SMEM_DYN>>>(x, emb);
    k_refine<<<N_TOK / 8, 256>>>(x, emb);
    k_quant <<<QPARTS, 256>>>(x, emb, out + 1);
    k_enc   <<<N_TOK / 256, 256>>>(out, has_full ? enc_elems : 0);
    k_final <<<1, 256>>>(out, has_full);
}

// round 10
// speedup vs baseline: 1.3283x; 1.2813x over previous
#include <cuda_runtime.h>
#include <cuda_bf16.h>
#include <cstdint>

// ---------------------------------------------------------------------------
// VQ-VAE VectorQuantizer on GB300 (sm_103, no 'a' features available in PTX).
// bf16 mma.sync approx distances -> rigorous window candidate filter ->
// exact sequential fp32-FMA refine (bit-identical to XLA, rel_err=0.0).
// R10: warp-specialized k_mma (8 MMA warps + 4 producer warps, bf16 codebook
// precomputed), atomic-free candidate capture, fused zero+scatter encodings.
// ---------------------------------------------------------------------------

#define N_TOK   16384
#define N_CODE  8192
#define C_DIM   256
#define Q_ELEMS 4194304      // 16*256*32*32
#define ENC_OFF 4194306LL    // 1 + Q_ELEMS + 1
#define SLOT    32           // candidate slots per (token, lane-quad position)
#define QPARTS  512

__device__ float          g_S[N_TOK];
__device__ float          g_L1[N_TOK];
__device__ float          g_E2[N_CODE];
__device__ int            g_idx[N_TOK];
__device__ int            g_counts[N_CODE];
__device__ double         g_loss_part[QPARTS];
__device__ int            g_cand[N_TOK][4 * SLOT];
__device__ int            g_cnt4[N_TOK][4];
__device__ unsigned       g_maxe_bits;
__device__ __nv_bfloat16  g_embh[N_CODE * C_DIM];   // bf16 codebook (4MB)

__device__ __forceinline__ float f_inf() { return __int_as_float(0x7f800000); }

__device__ __forceinline__ uint32_t smem_u32(const void* p) {
    uint32_t a;
    asm("{ .reg .u64 t; cvta.to.shared.u64 t, %1; cvt.u32.u64 %0, t; }"
        : "=r"(a) : "l"(p));
    return a;
}
#define LDSM_X4(r0, r1, r2, r3, addr)                                          \
    asm volatile("ldmatrix.sync.aligned.m8n8.x4.shared.b16 {%0,%1,%2,%3}, [%4];" \
        : "=r"(r0), "=r"(r1), "=r"(r2), "=r"(r3) : "r"(addr))
#define MMA_BF16(c0, c1, c2, c3, a0, a1, a2, a3, b0, b1)                       \
    asm volatile("mma.sync.aligned.m16n8k16.row.col.f32.bf16.bf16.f32 "       \
        "{%0,%1,%2,%3},{%4,%5,%6,%7},{%8,%9},{%0,%1,%2,%3};"                  \
        : "+f"(c0), "+f"(c1), "+f"(c2), "+f"(c3)                               \
        : "r"(a0), "r"(a1), "r"(a2), "r"(a3), "r"(b0), "r"(b1))

// ---------------------------------------------------------------- reset ----
__global__ void k_reset() {
    int t = blockIdx.x * blockDim.x + threadIdx.x;
    if (t < N_CODE) g_counts[t] = 0;
    if (t == 0)     g_maxe_bits = 0;
}

// --------------------------------------- one-time emb -> bf16 conversion ----
__global__ void k_cvt(const float* __restrict__ emb) {
    int i = blockIdx.x * blockDim.x + threadIdx.x;   // 262144 threads, 8 vals ea
    const float4 v0 = *(const float4*)&emb[(size_t)i * 8];
    const float4 v1 = *(const float4*)&emb[(size_t)i * 8 + 4];
    __nv_bfloat162 h0 = __floats2bfloat162_rn(v0.x, v0.y);
    __nv_bfloat162 h1 = __floats2bfloat162_rn(v0.z, v0.w);
    __nv_bfloat162 h2 = __floats2bfloat162_rn(v1.x, v1.y);
    __nv_bfloat162 h3 = __floats2bfloat162_rn(v1.z, v1.w);
    uint4 pk;
    pk.x = *(uint32_t*)&h0; pk.y = *(uint32_t*)&h1;
    pk.z = *(uint32_t*)&h2; pk.w = *(uint32_t*)&h3;
    *(uint4*)&g_embh[(size_t)i * 8] = pk;
}

// ----------------------------------------------- S = sum(x*x), L1 = sum|x| --
__global__ void k_S(const float* __restrict__ x) {
    int n = blockIdx.x * blockDim.x + threadIdx.x;
    if (n >= N_TOK) return;
    int b = n >> 10, hw = n & 1023;
    const float* p = x + (size_t)b * 262144 + hw;
    float acc = 0.0f, l1 = 0.0f;
    for (int c = 0; c < C_DIM; c++) {
        float v = p[(size_t)c * 1024];
        acc = __fadd_rn(acc, __fmul_rn(v, v));
        l1 += fabsf(v);
    }
    g_S[n] = acc;
    g_L1[n] = l1;
}

// ----------------------------------------- E2 = sum(e*e), track max |e| ----
__global__ void k_E2(const float* __restrict__ emb) {
    int k = blockIdx.x * blockDim.x + threadIdx.x;
    if (k >= N_CODE) return;
    const float* p = emb + (size_t)k * C_DIM;
    float acc = 0.0f, mx = 0.0f;
    for (int c = 0; c < C_DIM; c++) {
        float v = p[c];
        acc = __fadd_rn(acc, __fmul_rn(v, v));
        mx = fmaxf(mx, fabsf(v));
    }
    g_E2[k] = acc;
    atomicMax(&g_maxe_bits, __float_as_uint(mx));   // positive: uint order == float order
}

// ----------------------- bf16 mma.sync approx distances + candidate filter --
// 384 threads: warps 0-7 = MMA+epilogue (consumers), warps 8-11 = E staging
// (producers; exactly 1 per SMSP). A resident in smem, E double-buffered.
#define RS      528              // padded row stride bytes (264 halves)
#define SM_E2S  0                // 2 x 128 f32
#define SM_A    1024             // 128 rows * 528B = 67584
#define SM_EB0  68608
#define SM_EB1  136192
#define SMEM_DYN 203776

__global__ void __launch_bounds__(384, 1)
k_mma(const float* __restrict__ x) {
    extern __shared__ char sm[];
    float* e2s = (float*)(sm + SM_E2S);
    const uint32_t sb = smem_u32(sm);
    const uint32_t sA = sb + SM_A;

    const int tid = threadIdx.x, w = tid >> 5, lane = tid & 31;
    const int mbase = blockIdx.x * 128;
    const int b     = mbase >> 10;
    const int hw0   = mbase & 1023;
    const float* xb = x + (size_t)b * 262144 + hw0;

    // ---- stage A: 128 tokens x 256 c, bf16, padded rows (all 384 threads) --
    for (int i = tid; i < 128 * 32; i += 384) {
        int m = i & 127, c0 = (i >> 7) * 8;
        float v0 = xb[(size_t)(c0 + 0) * 1024 + m];
        float v1 = xb[(size_t)(c0 + 1) * 1024 + m];
        float v2 = xb[(size_t)(c0 + 2) * 1024 + m];
        float v3 = xb[(size_t)(c0 + 3) * 1024 + m];
        float v4 = xb[(size_t)(c0 + 4) * 1024 + m];
        float v5 = xb[(size_t)(c0 + 5) * 1024 + m];
        float v6 = xb[(size_t)(c0 + 6) * 1024 + m];
        float v7 = xb[(size_t)(c0 + 7) * 1024 + m];
        __nv_bfloat162 h0 = __floats2bfloat162_rn(v0, v1);
        __nv_bfloat162 h1 = __floats2bfloat162_rn(v2, v3);
        __nv_bfloat162 h2 = __floats2bfloat162_rn(v4, v5);
        __nv_bfloat162 h3 = __floats2bfloat162_rn(v6, v7);
        uint4 pk;
        pk.x = *(uint32_t*)&h0; pk.y = *(uint32_t*)&h1;
        pk.z = *(uint32_t*)&h2; pk.w = *(uint32_t*)&h3;
        *(uint4*)(sm + SM_A + m * RS + c0 * 2) = pk;
    }

    // ---- E tile copy from bf16 codebook (pure 16B moves) ----
    auto stage_E = [&](int nt, int buf, int t0, int nth) {
        const int kb = nt * 128;
        char* eb = sm + (buf ? SM_EB1 : SM_EB0);
        for (int i = t0; i < 4096; i += nth) {           // 128 rows x 32 chunks
            int row = i >> 5, c16 = (i & 31);
            uint4 v = *(const uint4*)&g_embh[(size_t)(kb + row) * 256 + c16 * 8];
            *(uint4*)(eb + row * RS + c16 * 16) = v;
        }
        for (int i = t0; i < 128; i += nth) e2s[buf * 128 + i] = g_E2[kb + i];
    };

    stage_E(0, 0, tid, 384);
    __syncthreads();

    if (w >= 8) {
        // ----------------------------- producer warps: stage ahead ---------
        const int pt = tid - 256;                        // 0..127
        for (int nt = 0; nt < 64; nt++) {
            if (nt + 1 < 64) stage_E(nt + 1, (nt + 1) & 1, pt, 128);
            __syncthreads();
        }
        return;
    }

    // --------------------------------- consumer warps: MMA + filter --------
    // hoist A fragments: 16 k-steps x 4 regs
    uint32_t a[16][4];
    {
        uint32_t abase = sA + (uint32_t)(w * 16 + (lane & 15)) * RS + ((lane >> 4) & 1) * 16;
#pragma unroll
        for (int k = 0; k < 16; k++)
            LDSM_X4(a[k][0], a[k][1], a[k][2], a[k][3], abase + k * 32);
    }

    const int   tok0 = mbase + w * 16 + (lane >> 2);
    const int   tok1 = tok0 + 8;
    const int   sub  = (lane & 3) * SLOT;
    const float S0 = g_S[tok0], S1 = g_S[tok1];
    const float maxe = __uint_as_float(g_maxe_bits);
    const float W0 = __fmaf_rn(0.0313f * maxe, g_L1[tok0], 1.3e-4f);
    const float W1 = __fmaf_rn(0.0313f * maxe, g_L1[tok1], 1.3e-4f);
    float rm0 = f_inf(), rm1 = f_inf(), thr0 = f_inf(), thr1 = f_inf();
    int   c0n = 0, c1n = 0;

    for (int nt = 0; nt < 64; nt++) {
        const uint32_t eB = sb + ((nt & 1) ? SM_EB1 : SM_EB0);
        const float*   e2 = e2s + (nt & 1) * 128;
        const int      kb = nt * 128;
        const uint32_t bbase = eB + (uint32_t)(lane & 15) * RS + ((lane >> 4) & 1) * 16;

#pragma unroll 1
        for (int fq = 0; fq < 2; fq++) {
            float acc[4][8];
#pragma unroll
            for (int q = 0; q < 4; q++)
#pragma unroll
                for (int r = 0; r < 8; r++) acc[q][r] = 0.f;

            const uint32_t bq = bbase + (uint32_t)fq * (64 * RS);

            uint32_t bb[2][4][4];
#pragma unroll
            for (int q = 0; q < 4; q++)
                LDSM_X4(bb[0][q][0], bb[0][q][1], bb[0][q][2], bb[0][q][3],
                        bq + (uint32_t)q * (16 * RS));
#pragma unroll
            for (int k = 0; k < 16; k++) {
                const int p = k & 1;
                if (k < 15) {
#pragma unroll
                    for (int q = 0; q < 4; q++)
                        LDSM_X4(bb[p ^ 1][q][0], bb[p ^ 1][q][1],
                                bb[p ^ 1][q][2], bb[p ^ 1][q][3],
                                bq + (uint32_t)q * (16 * RS) + (k + 1) * 32);
                }
#pragma unroll
                for (int q = 0; q < 4; q++) {
                    MMA_BF16(acc[q][0], acc[q][1], acc[q][2], acc[q][3],
                             a[k][0], a[k][1], a[k][2], a[k][3],
                             bb[p][q][0], bb[p][q][2]);
                    MMA_BF16(acc[q][4], acc[q][5], acc[q][6], acc[q][7],
                             a[k][0], a[k][1], a[k][2], a[k][3],
                             bb[p][q][1], bb[p][q][3]);
                }
            }

            // epilogue: d = (S + E2) - 2*dot ; atomic-free candidate capture
#pragma unroll
            for (int q = 0; q < 4; q++) {
                const int fp = fq * 4 + q;
#pragma unroll
                for (int h = 0; h < 2; h++) {
                    const int   f   = fp * 2 + h;
                    const int   cA  = f * 8 + (lane & 3) * 2;
                    const float e2a = e2[cA], e2b = e2[cA + 1];
                    const int   colA = kb + cA, colB = colA + 1;
                    const float dotA0 = h ? acc[q][4] : acc[q][0];
                    const float dotB0 = h ? acc[q][5] : acc[q][1];
                    const float dotA1 = h ? acc[q][6] : acc[q][2];
                    const float dotB1 = h ? acc[q][7] : acc[q][3];
                    float dA0 = __fsub_rn(__fadd_rn(S0, e2a), __fmul_rn(2.0f, dotA0));
                    float dB0 = __fsub_rn(__fadd_rn(S0, e2b), __fmul_rn(2.0f, dotB0));
                    float dA1 = __fsub_rn(__fadd_rn(S1, e2a), __fmul_rn(2.0f, dotA1));
                    float dB1 = __fsub_rn(__fadd_rn(S1, e2b), __fmul_rn(2.0f, dotB1));
                    if (dA0 < thr0) {
                        if (c0n < SLOT) g_cand[tok0][sub + c0n] = colA;
                        c0n++;
                        if (dA0 < rm0) { rm0 = dA0; thr0 = __fadd_rn(dA0, W0); }
                    }
                    if (dB0 < thr0) {
                        if (c0n < SLOT) g_cand[tok0][sub + c0n] = colB;
                        c0n++;
                        if (dB0 < rm0) { rm0 = dB0; thr0 = __fadd_rn(dB0, W0); }
                    }
                    if (dA1 < thr1) {
                        if (c1n < SLOT) g_cand[tok1][sub + c1n] = colA;
                        c1n++;
                        if (dA1 < rm1) { rm1 = dA1; thr1 = __fadd_rn(dA1, W1); }
                    }
                    if (dB1 < thr1) {
                        if (c1n < SLOT) g_cand[tok1][sub + c1n] = colB;
                        c1n++;
                        if (dB1 < rm1) { rm1 = dB1; thr1 = __fadd_rn(dB1, W1); }
                    }
                }
            }
            // tighten thresholds across the 4 lanes sharing the token rows
#pragma unroll
            for (int off = 1; off < 4; off <<= 1) {
                rm0 = fminf(rm0, __shfl_xor_sync(0xffffffff, rm0, off));
                rm1 = fminf(rm1, __shfl_xor_sync(0xffffffff, rm1, off));
            }
            thr0 = __fadd_rn(rm0, W0);
            thr1 = __fadd_rn(rm1, W1);
        }
        __syncthreads();
    }

    g_cnt4[tok0][lane & 3] = c0n;
    g_cnt4[tok1][lane & 3] = c1n;
}

// ------------------------------------- exact refinement (bit-exact argmin) --
__global__ void k_refine(const float* __restrict__ x, const float* __restrict__ emb) {
    __shared__ float xs[8][256];
    const int w = threadIdx.x >> 5, lane = threadIdx.x & 31;
    const int n = blockIdx.x * 8 + w;
    const int b = n >> 10, hw = n & 1023;
    const float* xb = x + (size_t)b * 262144 + hw;
    for (int c = lane; c < 256; c += 32) xs[w][c] = xb[(size_t)c * 1024];
    __syncwarp();

    const float S = g_S[n];
    int c4[4];
    c4[0] = g_cnt4[n][0]; c4[1] = g_cnt4[n][1];
    c4[2] = g_cnt4[n][2]; c4[3] = g_cnt4[n][3];
    const bool ovf = (c4[0] > SLOT) | (c4[1] > SLOT) | (c4[2] > SLOT) | (c4[3] > SLOT);
    const int total = c4[0] + c4[1] + c4[2] + c4[3];
    float bd = f_inf(); int bi = 0x7fffffff;

    auto exact_d = [&](int k) -> float {
        const float* e = emb + (size_t)k * 256;
        float acc = 0.0f;
#pragma unroll 8
        for (int c = 0; c < 256; c++)
            acc = __fmaf_rn(xs[w][c], e[c], acc);       // sequential chain, c asc
        float t = __fadd_rn(S, g_E2[k]);
        return __fsub_rn(t, __fmul_rn(2.0f, acc));
    };

    if (ovf) {                                          // overflow: full scan
        for (int k = lane; k < N_CODE; k += 32) {
            float d = exact_d(k);
            if (d < bd || (d == bd && k < bi)) { bd = d; bi = k; }
        }
    } else {
        for (int ci = lane; ci < total; ci += 32) {
            int r = ci, p = 0;
            while (r >= c4[p]) { r -= c4[p]; p++; }
            int k = g_cand[n][p * SLOT + r];
            float d = exact_d(k);
            if (d < bd || (d == bd && k < bi)) { bd = d; bi = k; }
        }
    }
#pragma unroll
    for (int off = 16; off > 0; off >>= 1) {
        float od = __shfl_down_sync(0xffffffff, bd, off);
        int   oi = __shfl_down_sync(0xffffffff, bi, off);
        if (od < bd || (od == bd && oi < bi)) { bd = od; bi = oi; }
    }
    if (lane == 0) g_idx[n] = bi;
}

// ---------------- quantized output + loss partial (smem row-gather) ---------
__global__ void __launch_bounds__(256)
k_quant(const float* __restrict__ x, const float* __restrict__ emb,
        float* __restrict__ outq) {
    __shared__ float  er[32][257];
    __shared__ int    sidx[32];
    __shared__ double sred[256];
    const int tid = threadIdx.x;
    const int n0  = blockIdx.x * 32;
    const int b   = n0 >> 10;
    const int hw0 = n0 & 1023;

    if (tid < 32) sidx[tid] = g_idx[n0 + tid];
    __syncthreads();
    for (int i = tid; i < 32 * 256; i += 256) {
        int row = i >> 8, c = i & 255;
        er[row][c] = emb[(size_t)sidx[row] * 256 + c];
    }
    __syncthreads();

    const int hwl = tid & 31;
    double part = 0.0;
    for (int c = tid >> 5; c < 256; c += 8) {
        size_t l = (size_t)b * 262144 + (size_t)c * 1024 + hw0 + hwl;
        float xv   = x[l];
        float q    = er[hwl][c];
        float diff = __fsub_rn(q, xv);
        outq[l]    = __fadd_rn(xv, diff);               // straight-through
        part += (double)__fmul_rn(diff, diff);
    }

    sred[tid] = part;
    __syncthreads();
    for (int s = 128; s > 0; s >>= 1) {
        if (tid < s) sred[tid] += sred[tid + s];
        __syncthreads();
    }
    if (tid == 0) g_loss_part[blockIdx.x] = sred[0];
}

// --------------- fused encodings zero + one-hot scatter + histogram ---------
// One warp per token row: write all 8192 floats (zeros + single 1.0).
// ENC_OFF is only 8B-aligned -> float2 stores.
__global__ void __launch_bounds__(256)
k_enc(float* __restrict__ out) {
    const int w    = threadIdx.x >> 5, lane = threadIdx.x & 31;
    const int row  = blockIdx.x * 8 + w;
    const int idx  = g_idx[row];
    float2* dst = (float2*)(out + ENC_OFF) + (size_t)row * 4096;
    const int hot = idx >> 1;
    const float2 z = make_float2(0.0f, 0.0f);
#pragma unroll 8
    for (int j = 0; j < 128; j++) {
        int pos = j * 32 + lane;
        float2 v = z;
        if (pos == hot) {                                // rare: once per warp
            if (idx & 1) v.y = 1.0f; else v.x = 1.0f;
        }
        dst[pos] = v;
    }
    if (lane == 0) atomicAdd(&g_counts[idx], 1);
}

// -------------------------------------------------- loss + perplexity -------
__global__ void k_final(float* __restrict__ out, int has_full) {
    __shared__ double sred[256];
    int t = threadIdx.x;
    double acc = 0.0;
    for (int k = t; k < N_CODE; k += 256) {
        float p  = (float)g_counts[k] * (1.0f / 16384.0f);
        float lg = logf(__fadd_rn(p, 1e-10f));
        acc += (double)__fmul_rn(p, lg);
    }
    sred[t] = acc; __syncthreads();
    for (int s = 128; s > 0; s >>= 1) {
        if (t < s) sred[t] += sred[t + s];
        __syncthreads();
    }
    double H = sred[0];

    double lacc = 0.0;
    for (int k = t; k < QPARTS; k += 256) lacc += g_loss_part[k];
    __syncthreads();
    sred[t] = lacc; __syncthreads();
    for (int s = 128; s > 0; s >>= 1) {
        if (t < s) sred[t] += sred[t + s];
        __syncthreads();
    }
    if (t == 0) {
        float m    = (float)(sred[0] / (double)Q_ELEMS);
        float loss = __fadd_rn(m, __fmul_rn(0.25f, m));
        out[0] = loss;
        if (has_full) out[1 + Q_ELEMS] = expf(-(float)H);
    }
}

// ---------------------------------------------------------------------------
extern "C" void kernel_launch(void* const* d_in, const int* in_sizes, int n_in,
                              void* d_out, int out_size) {
    const float* x   = (const float*)d_in[0];
    const float* emb = (const float*)d_in[1];
    if (n_in >= 2 && in_sizes[0] == N_CODE * C_DIM && in_sizes[1] == Q_ELEMS) {
        const float* t = x; x = emb; emb = t;
    }
    float* out = (float*)d_out;

    long long enc_elems = (long long)out_size - ENC_OFF;
    int has_full = (enc_elems >= (long long)N_TOK * N_CODE);

    cudaFuncSetAttribute(k_mma, cudaFuncAttributeMaxDynamicSharedMemorySize,
                         SMEM_DYN);

    k_reset <<<32, 256>>>();
    k_cvt   <<<1024, 256>>>(emb);
    k_S     <<<N_TOK / 256, 256>>>(x);
    k_E2    <<<N_CODE / 256, 256>>>(emb);
    k_mma   <<<N_TOK / 128, 384, SMEM_DYN>>>(x);
    k_refine<<<N_TOK / 8, 256>>>(x, emb);
    k_quant <<<QPARTS, 256>>>(x, emb, out + 1);
    if (has_full)
        k_enc<<<N_TOK / 8, 256>>>(out);
    else if (enc_elems > 0)
        cudaMemsetAsync(out + ENC_OFF, 0, (size_t)enc_elems * sizeof(float), 0);
    k_final <<<1, 256>>>(out, has_full);
}

// round 11
// speedup vs baseline: 2.2159x; 1.6683x over previous
#include <cuda_runtime.h>
#include <cuda_bf16.h>
#include <cstdint>

// ---------------------------------------------------------------------------
// VQ-VAE VectorQuantizer on GB300 (sm_103, no 'a' features available in PTX).
// bf16 mma.sync approx distances -> rigorous window candidate filter ->
// exact sequential fp32-FMA refine (bit-identical to XLA, rel_err=0.0).
// R11: kill L1tex wavefront replays in k_refine / k_E2 via float4 row loads
// (rounding chains unchanged); k_quant float4 gather.
// ---------------------------------------------------------------------------

#define N_TOK   16384
#define N_CODE  8192
#define C_DIM   256
#define Q_ELEMS 4194304      // 16*256*32*32
#define ENC_OFF 4194306LL    // 1 + Q_ELEMS + 1
#define SLOT    32           // candidate slots per (token, lane-quad position)
#define QPARTS  512

__device__ float          g_S[N_TOK];
__device__ float          g_L1[N_TOK];
__device__ float          g_E2[N_CODE];
__device__ int            g_idx[N_TOK];
__device__ int            g_counts[N_CODE];
__device__ double         g_loss_part[QPARTS];
__device__ int            g_cand[N_TOK][4 * SLOT];
__device__ int            g_cnt4[N_TOK][4];
__device__ unsigned       g_maxe_bits;
__device__ __nv_bfloat16  g_embh[N_CODE * C_DIM];   // bf16 codebook (4MB)

__device__ __forceinline__ float f_inf() { return __int_as_float(0x7f800000); }

__device__ __forceinline__ uint32_t smem_u32(const void* p) {
    uint32_t a;
    asm("{ .reg .u64 t; cvta.to.shared.u64 t, %1; cvt.u32.u64 %0, t; }"
        : "=r"(a) : "l"(p));
    return a;
}
#define LDSM_X4(r0, r1, r2, r3, addr)                                          \
    asm volatile("ldmatrix.sync.aligned.m8n8.x4.shared.b16 {%0,%1,%2,%3}, [%4];" \
        : "=r"(r0), "=r"(r1), "=r"(r2), "=r"(r3) : "r"(addr))
#define MMA_BF16(c0, c1, c2, c3, a0, a1, a2, a3, b0, b1)                       \
    asm volatile("mma.sync.aligned.m16n8k16.row.col.f32.bf16.bf16.f32 "       \
        "{%0,%1,%2,%3},{%4,%5,%6,%7},{%8,%9},{%0,%1,%2,%3};"                  \
        : "+f"(c0), "+f"(c1), "+f"(c2), "+f"(c3)                               \
        : "r"(a0), "r"(a1), "r"(a2), "r"(a3), "r"(b0), "r"(b1))

// ---------------------------------------------------------------- reset ----
__global__ void k_reset() {
    int t = blockIdx.x * blockDim.x + threadIdx.x;
    if (t < N_CODE) g_counts[t] = 0;
    if (t == 0)     g_maxe_bits = 0;
}

// --------------------------------------- one-time emb -> bf16 conversion ----
__global__ void k_cvt(const float* __restrict__ emb) {
    int i = blockIdx.x * blockDim.x + threadIdx.x;   // 262144 threads, 8 vals ea
    const float4 v0 = *(const float4*)&emb[(size_t)i * 8];
    const float4 v1 = *(const float4*)&emb[(size_t)i * 8 + 4];
    __nv_bfloat162 h0 = __floats2bfloat162_rn(v0.x, v0.y);
    __nv_bfloat162 h1 = __floats2bfloat162_rn(v0.z, v0.w);
    __nv_bfloat162 h2 = __floats2bfloat162_rn(v1.x, v1.y);
    __nv_bfloat162 h3 = __floats2bfloat162_rn(v1.z, v1.w);
    uint4 pk;
    pk.x = *(uint32_t*)&h0; pk.y = *(uint32_t*)&h1;
    pk.z = *(uint32_t*)&h2; pk.w = *(uint32_t*)&h3;
    *(uint4*)&g_embh[(size_t)i * 8] = pk;
}

// ----------------------------------------------- S = sum(x*x), L1 = sum|x| --
__global__ void k_S(const float* __restrict__ x) {
    int n = blockIdx.x * blockDim.x + threadIdx.x;
    if (n >= N_TOK) return;
    int b = n >> 10, hw = n & 1023;
    const float* p = x + (size_t)b * 262144 + hw;
    float acc = 0.0f, l1 = 0.0f;
    for (int c = 0; c < C_DIM; c++) {
        float v = p[(size_t)c * 1024];
        acc = __fadd_rn(acc, __fmul_rn(v, v));
        l1 += fabsf(v);
    }
    g_S[n] = acc;
    g_L1[n] = l1;
}

// ----------------------------------------- E2 = sum(e*e), track max |e| ----
// float4 row loads (4x fewer L1 wavefronts); per-code chain order unchanged.
__global__ void k_E2(const float* __restrict__ emb) {
    int k = blockIdx.x * blockDim.x + threadIdx.x;
    if (k >= N_CODE) return;
    const float4* p = (const float4*)(emb + (size_t)k * C_DIM);
    float acc = 0.0f, mx = 0.0f;
#pragma unroll 8
    for (int c4 = 0; c4 < C_DIM / 4; c4++) {
        float4 v = __ldg(&p[c4]);
        acc = __fadd_rn(acc, __fmul_rn(v.x, v.x));
        acc = __fadd_rn(acc, __fmul_rn(v.y, v.y));
        acc = __fadd_rn(acc, __fmul_rn(v.z, v.z));
        acc = __fadd_rn(acc, __fmul_rn(v.w, v.w));
        mx = fmaxf(mx, fmaxf(fmaxf(fabsf(v.x), fabsf(v.y)),
                             fmaxf(fabsf(v.z), fabsf(v.w))));
    }
    g_E2[k] = acc;
    atomicMax(&g_maxe_bits, __float_as_uint(mx));   // positive: uint order == float order
}

// ----------------------- bf16 mma.sync approx distances + candidate filter --
// 384 threads: warps 0-7 = MMA+epilogue (consumers), warps 8-11 = E staging
// (producers; exactly 1 per SMSP). A resident in smem, E double-buffered.
#define RS      528              // padded row stride bytes (264 halves)
#define SM_E2S  0                // 2 x 128 f32
#define SM_A    1024             // 128 rows * 528B = 67584
#define SM_EB0  68608
#define SM_EB1  136192
#define SMEM_DYN 203776

__global__ void __launch_bounds__(384, 1)
k_mma(const float* __restrict__ x) {
    extern __shared__ char sm[];
    float* e2s = (float*)(sm + SM_E2S);
    const uint32_t sb = smem_u32(sm);
    const uint32_t sA = sb + SM_A;

    const int tid = threadIdx.x, w = tid >> 5, lane = tid & 31;
    const int mbase = blockIdx.x * 128;
    const int b     = mbase >> 10;
    const int hw0   = mbase & 1023;
    const float* xb = x + (size_t)b * 262144 + hw0;

    // ---- stage A: 128 tokens x 256 c, bf16, padded rows (all 384 threads) --
    for (int i = tid; i < 128 * 32; i += 384) {
        int m = i & 127, c0 = (i >> 7) * 8;
        float v0 = xb[(size_t)(c0 + 0) * 1024 + m];
        float v1 = xb[(size_t)(c0 + 1) * 1024 + m];
        float v2 = xb[(size_t)(c0 + 2) * 1024 + m];
        float v3 = xb[(size_t)(c0 + 3) * 1024 + m];
        float v4 = xb[(size_t)(c0 + 4) * 1024 + m];
        float v5 = xb[(size_t)(c0 + 5) * 1024 + m];
        float v6 = xb[(size_t)(c0 + 6) * 1024 + m];
        float v7 = xb[(size_t)(c0 + 7) * 1024 + m];
        __nv_bfloat162 h0 = __floats2bfloat162_rn(v0, v1);
        __nv_bfloat162 h1 = __floats2bfloat162_rn(v2, v3);
        __nv_bfloat162 h2 = __floats2bfloat162_rn(v4, v5);
        __nv_bfloat162 h3 = __floats2bfloat162_rn(v6, v7);
        uint4 pk;
        pk.x = *(uint32_t*)&h0; pk.y = *(uint32_t*)&h1;
        pk.z = *(uint32_t*)&h2; pk.w = *(uint32_t*)&h3;
        *(uint4*)(sm + SM_A + m * RS + c0 * 2) = pk;
    }

    // ---- E tile copy from bf16 codebook (pure 16B moves) ----
    auto stage_E = [&](int nt, int buf, int t0, int nth) {
        const int kb = nt * 128;
        char* eb = sm + (buf ? SM_EB1 : SM_EB0);
        for (int i = t0; i < 4096; i += nth) {           // 128 rows x 32 chunks
            int row = i >> 5, c16 = (i & 31);
            uint4 v = *(const uint4*)&g_embh[(size_t)(kb + row) * 256 + c16 * 8];
            *(uint4*)(eb + row * RS + c16 * 16) = v;
        }
        for (int i = t0; i < 128; i += nth) e2s[buf * 128 + i] = g_E2[kb + i];
    };

    stage_E(0, 0, tid, 384);
    __syncthreads();

    if (w >= 8) {
        // ----------------------------- producer warps: stage ahead ---------
        const int pt = tid - 256;                        // 0..127
        for (int nt = 0; nt < 64; nt++) {
            if (nt + 1 < 64) stage_E(nt + 1, (nt + 1) & 1, pt, 128);
            __syncthreads();
        }
        return;
    }

    // --------------------------------- consumer warps: MMA + filter --------
    // hoist A fragments: 16 k-steps x 4 regs
    uint32_t a[16][4];
    {
        uint32_t abase = sA + (uint32_t)(w * 16 + (lane & 15)) * RS + ((lane >> 4) & 1) * 16;
#pragma unroll
        for (int k = 0; k < 16; k++)
            LDSM_X4(a[k][0], a[k][1], a[k][2], a[k][3], abase + k * 32);
    }

    const int   tok0 = mbase + w * 16 + (lane >> 2);
    const int   tok1 = tok0 + 8;
    const int   sub  = (lane & 3) * SLOT;
    const float S0 = g_S[tok0], S1 = g_S[tok1];
    const float maxe = __uint_as_float(g_maxe_bits);
    const float W0 = __fmaf_rn(0.0313f * maxe, g_L1[tok0], 1.3e-4f);
    const float W1 = __fmaf_rn(0.0313f * maxe, g_L1[tok1], 1.3e-4f);
    float rm0 = f_inf(), rm1 = f_inf(), thr0 = f_inf(), thr1 = f_inf();
    int   c0n = 0, c1n = 0;

    for (int nt = 0; nt < 64; nt++) {
        const uint32_t eB = sb + ((nt & 1) ? SM_EB1 : SM_EB0);
        const float*   e2 = e2s + (nt & 1) * 128;
        const int      kb = nt * 128;
        const uint32_t bbase = eB + (uint32_t)(lane & 15) * RS + ((lane >> 4) & 1) * 16;

#pragma unroll 1
        for (int fq = 0; fq < 2; fq++) {
            float acc[4][8];
#pragma unroll
            for (int q = 0; q < 4; q++)
#pragma unroll
                for (int r = 0; r < 8; r++) acc[q][r] = 0.f;

            const uint32_t bq = bbase + (uint32_t)fq * (64 * RS);

            uint32_t bb[2][4][4];
#pragma unroll
            for (int q = 0; q < 4; q++)
                LDSM_X4(bb[0][q][0], bb[0][q][1], bb[0][q][2], bb[0][q][3],
                        bq + (uint32_t)q * (16 * RS));
#pragma unroll
            for (int k = 0; k < 16; k++) {
                const int p = k & 1;
                if (k < 15) {
#pragma unroll
                    for (int q = 0; q < 4; q++)
                        LDSM_X4(bb[p ^ 1][q][0], bb[p ^ 1][q][1],
                                bb[p ^ 1][q][2], bb[p ^ 1][q][3],
                                bq + (uint32_t)q * (16 * RS) + (k + 1) * 32);
                }
#pragma unroll
                for (int q = 0; q < 4; q++) {
                    MMA_BF16(acc[q][0], acc[q][1], acc[q][2], acc[q][3],
                             a[k][0], a[k][1], a[k][2], a[k][3],
                             bb[p][q][0], bb[p][q][2]);
                    MMA_BF16(acc[q][4], acc[q][5], acc[q][6], acc[q][7],
                             a[k][0], a[k][1], a[k][2], a[k][3],
                             bb[p][q][1], bb[p][q][3]);
                }
            }

            // epilogue: d = (S + E2) - 2*dot ; atomic-free candidate capture
#pragma unroll
            for (int q = 0; q < 4; q++) {
                const int fp = fq * 4 + q;
#pragma unroll
                for (int h = 0; h < 2; h++) {
                    const int   f   = fp * 2 + h;
                    const int   cA  = f * 8 + (lane & 3) * 2;
                    const float e2a = e2[cA], e2b = e2[cA + 1];
                    const int   colA = kb + cA, colB = colA + 1;
                    const float dotA0 = h ? acc[q][4] : acc[q][0];
                    const float dotB0 = h ? acc[q][5] : acc[q][1];
                    const float dotA1 = h ? acc[q][6] : acc[q][2];
                    const float dotB1 = h ? acc[q][7] : acc[q][3];
                    float dA0 = __fsub_rn(__fadd_rn(S0, e2a), __fmul_rn(2.0f, dotA0));
                    float dB0 = __fsub_rn(__fadd_rn(S0, e2b), __fmul_rn(2.0f, dotB0));
                    float dA1 = __fsub_rn(__fadd_rn(S1, e2a), __fmul_rn(2.0f, dotA1));
                    float dB1 = __fsub_rn(__fadd_rn(S1, e2b), __fmul_rn(2.0f, dotB1));
                    if (dA0 < thr0) {
                        if (c0n < SLOT) g_cand[tok0][sub + c0n] = colA;
                        c0n++;
                        if (dA0 < rm0) { rm0 = dA0; thr0 = __fadd_rn(dA0, W0); }
                    }
                    if (dB0 < thr0) {
                        if (c0n < SLOT) g_cand[tok0][sub + c0n] = colB;
                        c0n++;
                        if (dB0 < rm0) { rm0 = dB0; thr0 = __fadd_rn(dB0, W0); }
                    }
                    if (dA1 < thr1) {
                        if (c1n < SLOT) g_cand[tok1][sub + c1n] = colA;
                        c1n++;
                        if (dA1 < rm1) { rm1 = dA1; thr1 = __fadd_rn(dA1, W1); }
                    }
                    if (dB1 < thr1) {
                        if (c1n < SLOT) g_cand[tok1][sub + c1n] = colB;
                        c1n++;
                        if (dB1 < rm1) { rm1 = dB1; thr1 = __fadd_rn(dB1, W1); }
                    }
                }
            }
            // tighten thresholds across the 4 lanes sharing the token rows
#pragma unroll
            for (int off = 1; off < 4; off <<= 1) {
                rm0 = fminf(rm0, __shfl_xor_sync(0xffffffff, rm0, off));
                rm1 = fminf(rm1, __shfl_xor_sync(0xffffffff, rm1, off));
            }
            thr0 = __fadd_rn(rm0, W0);
            thr1 = __fadd_rn(rm1, W1);
        }
        __syncthreads();
    }

    g_cnt4[tok0][lane & 3] = c0n;
    g_cnt4[tok1][lane & 3] = c1n;
}

// ------------------------------------- exact refinement (bit-exact argmin) --
// float4 row loads: 4x fewer L1 wavefronts; per-candidate FMA chain remains
// strictly sequential over c ascending (bitwise identical result).
__global__ void k_refine(const float* __restrict__ x, const float* __restrict__ emb) {
    __shared__ float xs[8][256];
    const int w = threadIdx.x >> 5, lane = threadIdx.x & 31;
    const int n = blockIdx.x * 8 + w;
    const int b = n >> 10, hw = n & 1023;
    const float* xb = x + (size_t)b * 262144 + hw;
    for (int c = lane; c < 256; c += 32) xs[w][c] = xb[(size_t)c * 1024];
    __syncwarp();

    const float S = g_S[n];
    int c4[4];
    c4[0] = g_cnt4[n][0]; c4[1] = g_cnt4[n][1];
    c4[2] = g_cnt4[n][2]; c4[3] = g_cnt4[n][3];
    const bool ovf = (c4[0] > SLOT) | (c4[1] > SLOT) | (c4[2] > SLOT) | (c4[3] > SLOT);
    const int total = c4[0] + c4[1] + c4[2] + c4[3];
    float bd = f_inf(); int bi = 0x7fffffff;

    auto exact_d = [&](int k) -> float {
        const float4* e = (const float4*)(emb + (size_t)k * 256);
        const float4* xv4 = (const float4*)xs[w];
        float acc = 0.0f;
#pragma unroll 8
        for (int c4i = 0; c4i < 64; c4i++) {
            float4 ev = __ldg(&e[c4i]);
            float4 xv = xv4[c4i];
            acc = __fmaf_rn(xv.x, ev.x, acc);
            acc = __fmaf_rn(xv.y, ev.y, acc);
            acc = __fmaf_rn(xv.z, ev.z, acc);
            acc = __fmaf_rn(xv.w, ev.w, acc);
        }
        float t = __fadd_rn(S, g_E2[k]);
        return __fsub_rn(t, __fmul_rn(2.0f, acc));
    };

    if (ovf) {                                          // overflow: full scan
        for (int k = lane; k < N_CODE; k += 32) {
            float d = exact_d(k);
            if (d < bd || (d == bd && k < bi)) { bd = d; bi = k; }
        }
    } else {
        for (int ci = lane; ci < total; ci += 32) {
            int r = ci, p = 0;
            while (r >= c4[p]) { r -= c4[p]; p++; }
            int k = g_cand[n][p * SLOT + r];
            float d = exact_d(k);
            if (d < bd || (d == bd && k < bi)) { bd = d; bi = k; }
        }
    }
#pragma unroll
    for (int off = 16; off > 0; off >>= 1) {
        float od = __shfl_down_sync(0xffffffff, bd, off);
        int   oi = __shfl_down_sync(0xffffffff, bi, off);
        if (od < bd || (od == bd && oi < bi)) { bd = od; bi = oi; }
    }
    if (lane == 0) g_idx[n] = bi;
}

// ---------------- quantized output + loss partial (smem row-gather) ---------
__global__ void __launch_bounds__(256)
k_quant(const float* __restrict__ x, const float* __restrict__ emb,
        float* __restrict__ outq) {
    __shared__ float  er[32][257];
    __shared__ int    sidx[32];
    __shared__ double sred[256];
    const int tid = threadIdx.x;
    const int n0  = blockIdx.x * 32;
    const int b   = n0 >> 10;
    const int hw0 = n0 & 1023;

    if (tid < 32) sidx[tid] = g_idx[n0 + tid];
    __syncthreads();
    for (int i = tid; i < 32 * 64; i += 256) {          // float4 gather
        int row = i >> 6, c4i = i & 63;
        float4 v = __ldg((const float4*)&emb[(size_t)sidx[row] * 256 + c4i * 4]);
        er[row][c4i * 4 + 0] = v.x;
        er[row][c4i * 4 + 1] = v.y;
        er[row][c4i * 4 + 2] = v.z;
        er[row][c4i * 4 + 3] = v.w;
    }
    __syncthreads();

    const int hwl = tid & 31;
    double part = 0.0;
    for (int c = tid >> 5; c < 256; c += 8) {
        size_t l = (size_t)b * 262144 + (size_t)c * 1024 + hw0 + hwl;
        float xv   = x[l];
        float q    = er[hwl][c];
        float diff = __fsub_rn(q, xv);
        outq[l]    = __fadd_rn(xv, diff);               // straight-through
        part += (double)__fmul_rn(diff, diff);
    }

    sred[tid] = part;
    __syncthreads();
    for (int s = 128; s > 0; s >>= 1) {
        if (tid < s) sred[tid] += sred[tid + s];
        __syncthreads();
    }
    if (tid == 0) g_loss_part[blockIdx.x] = sred[0];
}

// --------------- fused encodings zero + one-hot scatter + histogram ---------
__global__ void __launch_bounds__(256)
k_enc(float* __restrict__ out) {
    const int w    = threadIdx.x >> 5, lane = threadIdx.x & 31;
    const int row  = blockIdx.x * 8 + w;
    const int idx  = g_idx[row];
    float2* dst = (float2*)(out + ENC_OFF) + (size_t)row * 4096;
    const int hot = idx >> 1;
    const float2 z = make_float2(0.0f, 0.0f);
#pragma unroll 8
    for (int j = 0; j < 128; j++) {
        int pos = j * 32 + lane;
        float2 v = z;
        if (pos == hot) {                                // rare: once per warp
            if (idx & 1) v.y = 1.0f; else v.x = 1.0f;
        }
        dst[pos] = v;
    }
    if (lane == 0) atomicAdd(&g_counts[idx], 1);
}

// -------------------------------------------------- loss + perplexity -------
__global__ void k_final(float* __restrict__ out, int has_full) {
    __shared__ double sred[256];
    int t = threadIdx.x;
    double acc = 0.0;
    for (int k = t; k < N_CODE; k += 256) {
        float p  = (float)g_counts[k] * (1.0f / 16384.0f);
        float lg = logf(__fadd_rn(p, 1e-10f));
        acc += (double)__fmul_rn(p, lg);
    }
    sred[t] = acc; __syncthreads();
    for (int s = 128; s > 0; s >>= 1) {
        if (t < s) sred[t] += sred[t + s];
        __syncthreads();
    }
    double H = sred[0];

    double lacc = 0.0;
    for (int k = t; k < QPARTS; k += 256) lacc += g_loss_part[k];
    __syncthreads();
    sred[t] = lacc; __syncthreads();
    for (int s = 128; s > 0; s >>= 1) {
        if (t < s) sred[t] += sred[t + s];
        __syncthreads();
    }
    if (t == 0) {
        float m    = (float)(sred[0] / (double)Q_ELEMS);
        float loss = __fadd_rn(m, __fmul_rn(0.25f, m));
        out[0] = loss;
        if (has_full) out[1 + Q_ELEMS] = expf(-(float)H);
    }
}

// ---------------------------------------------------------------------------
extern "C" void kernel_launch(void* const* d_in, const int* in_sizes, int n_in,
                              void* d_out, int out_size) {
    const float* x   = (const float*)d_in[0];
    const float* emb = (const float*)d_in[1];
    if (n_in >= 2 && in_sizes[0] == N_CODE * C_DIM && in_sizes[1] == Q_ELEMS) {
        const float* t = x; x = emb; emb = t;
    }
    float* out = (float*)d_out;

    long long enc_elems = (long long)out_size - ENC_OFF;
    int has_full = (enc_elems >= (long long)N_TOK * N_CODE);

    cudaFuncSetAttribute(k_mma, cudaFuncAttributeMaxDynamicSharedMemorySize,
                         SMEM_DYN);

    k_reset <<<32, 256>>>();
    k_cvt   <<<1024, 256>>>(emb);
    k_S     <<<N_TOK / 256, 256>>>(x);
    k_E2    <<<64, 128>>>(emb);
    k_mma   <<<N_TOK / 128, 384, SMEM_DYN>>>(x);
    k_refine<<<N_TOK / 8, 256>>>(x, emb);
    k_quant <<<QPARTS, 256>>>(x, emb, out + 1);
    if (has_full)
        k_enc<<<N_TOK / 8, 256>>>(out);
    else if (enc_elems > 0)
        cudaMemsetAsync(out + ENC_OFF, 0, (size_t)enc_elems * sizeof(float), 0);
    k_final <<<1, 256>>>(out, has_full);
}